// round 2
// baseline (speedup 1.0000x reference)
#include <cuda_runtime.h>
#include <stdint.h>

// Welford estimator over the batch dim.
// Inputs (metadata order):
//   d_in[0]: x        float32  (B, S, H)   -> Nx = B*S*H elements
//   d_in[1]: mean     float32  (S, H)      -> Ns elements
//   d_in[2]: m2       float32  (S, H)
//   d_in[3]: nonzero  int32    (S, H)
//   d_in[4]: num_samples int32 scalar
// Output buffer is float32 throughout (flattened tuple, ints cast to float):
//   [0, Nx)              : x copy
//   [Nx, Nx+Ns)          : mean
//   [Nx+Ns, Nx+2Ns)      : m2
//   [Nx+2Ns, Nx+3Ns)     : nonzero AS FLOAT
//   [Nx+3Ns]             : num_samples AS FLOAT

__global__ void welford_kernel(const float4* __restrict__ x4,
                               const float4* __restrict__ mean_in,
                               const float4* __restrict__ m2_in,
                               const int4*   __restrict__ nz_in,
                               const int*    __restrict__ n_in,
                               float4* __restrict__ out_x,
                               float4* __restrict__ out_mean,
                               float4* __restrict__ out_m2,
                               float4* __restrict__ out_nz,
                               float*  __restrict__ out_n,
                               int nvec, int B)
{
    __shared__ float s_inv[64];   // reciprocals 1/(n0+b+1), b in [0,B)

    const int n0 = *n_in;

    // Per-block reciprocal table (uniform across grid; B divisions per block).
    if (threadIdx.x < B) {
        s_inv[threadIdx.x] = 1.0f / (float)(n0 + threadIdx.x + 1);
    }
    __syncthreads();

    const int idx = blockIdx.x * blockDim.x + threadIdx.x;   // float4 index in [0, nvec)
    if (idx >= nvec) return;

    float4 mean = mean_in[idx];
    float4 m2   = m2_in[idx];
    int4   nz   = nz_in[idx];

    #pragma unroll 4
    for (int b = 0; b < B; ++b) {
        const size_t off = (size_t)b * (size_t)nvec + (size_t)idx;
        float4 xi = __ldcs(&x4[off]);       // streaming read: no reuse
        __stcs(&out_x[off], xi);            // fused x copy-out

        const float inv = s_inv[b];

        // lane x
        nz.x += (xi.x != 0.0f);
        {
            float om = mean.x;
            mean.x = om + (xi.x - om) * inv;
            m2.x  += (xi.x - mean.x) * (xi.x - om);
        }
        // lane y
        nz.y += (xi.y != 0.0f);
        {
            float om = mean.y;
            mean.y = om + (xi.y - om) * inv;
            m2.y  += (xi.y - mean.y) * (xi.y - om);
        }
        // lane z
        nz.z += (xi.z != 0.0f);
        {
            float om = mean.z;
            mean.z = om + (xi.z - om) * inv;
            m2.z  += (xi.z - mean.z) * (xi.z - om);
        }
        // lane w
        nz.w += (xi.w != 0.0f);
        {
            float om = mean.w;
            mean.w = om + (xi.w - om) * inv;
            m2.w  += (xi.w - mean.w) * (xi.w - om);
        }
    }

    out_mean[idx] = mean;
    out_m2[idx]   = m2;

    // nonzero counts stored as FLOAT values (output buffer dtype is float32)
    float4 nzf;
    nzf.x = (float)nz.x;
    nzf.y = (float)nz.y;
    nzf.z = (float)nz.z;
    nzf.w = (float)nz.w;
    out_nz[idx] = nzf;

    if (idx == 0) {
        *out_n = (float)(n0 + B);
    }
}

extern "C" void kernel_launch(void* const* d_in, const int* in_sizes, int n_in,
                              void* d_out, int out_size)
{
    const float* x       = (const float*)d_in[0];
    const float* mean_in = (const float*)d_in[1];
    const float* m2_in   = (const float*)d_in[2];
    const int*   nz_in   = (const int*)d_in[3];
    const int*   ns_in   = (const int*)d_in[4];

    const int Nx = in_sizes[0];          // B*S*H = 67108864
    const int Ns = in_sizes[1];          // S*H   = 2097152
    const int B  = Nx / Ns;              // 32

    float* out   = (float*)d_out;
    float* out_x    = out;
    float* out_mean = out + (size_t)Nx;
    float* out_m2   = out + (size_t)Nx + (size_t)Ns;
    float* out_nz   = out + (size_t)Nx + 2*(size_t)Ns;
    float* out_n    = out + (size_t)Nx + 3*(size_t)Ns;

    const int nvec = Ns / 4;             // 524288 float4 positions
    const int threads = 256;
    const int blocks = (nvec + threads - 1) / threads;

    welford_kernel<<<blocks, threads>>>(
        (const float4*)x,
        (const float4*)mean_in,
        (const float4*)m2_in,
        (const int4*)nz_in,
        ns_in,
        (float4*)out_x,
        (float4*)out_mean,
        (float4*)out_m2,
        (float4*)out_nz,
        out_n,
        nvec, B);
}